// round 14
// baseline (speedup 1.0000x reference)
#include <cuda_runtime.h>
#include <math.h>
#include <stdint.h>

// Problem constants
#define B_  2
#define S_  2048
#define D_  2048
#define H_  16
#define HD_ 128
#define M_  (B_*S_)   // 4096 rows

// GEMM tiling (tf32 mma.sync): block 128(M) x 256(N) x 16(K), warp tile 64x64
#define BM 128
#define BN 256
#define BK 16
#define LDW 20        // BK + 4 pad words (pitch mod 32 == 20 -> conflict-free frags)

// Flash-attention tiling (round-7 config, best measured: 467.8 us)
#define FBR 128
#define FBC 64
#define QLD 132

// Scratch (device globals: allocation-free rule)
__device__ float g_q[(size_t)M_ * D_];    // Q in (B,H,S,HD) layout
__device__ float g_ctx[(size_t)M_ * D_];  // attention context in (B,S,D) layout

__device__ __forceinline__ uint32_t f2tf32(float x) {
    uint32_t u;
    asm("cvt.rna.tf32.f32 %0, %1;" : "=r"(u) : "f"(x));
    return u;
}

__device__ __forceinline__ void mma_tf32(float c[4], uint32_t a0, uint32_t a1,
                                         uint32_t a2, uint32_t a3,
                                         uint32_t b0, uint32_t b1) {
    asm volatile(
        "mma.sync.aligned.m16n8k8.row.col.f32.tf32.tf32.f32 "
        "{%0,%1,%2,%3}, {%4,%5,%6,%7}, {%8,%9}, {%0,%1,%2,%3};"
        : "+f"(c[0]), "+f"(c[1]), "+f"(c[2]), "+f"(c[3])
        : "r"(a0), "r"(a1), "r"(a2), "r"(a3), "r"(b0), "r"(b1));
}

// ---------------------------------------------------------------------------
// GEMM (tf32 mma.sync): Y = X @ W^T + bias.
// Block 128x256x16, 256 threads = 8 warps as 2(M) x 4(N), warp tile 64x64.
// LDS/mma = 1.0; STATIC smem 30.7 KB; small load temps (24 regs) to avoid
// the register-pressure spills that sank the BK=32 variant.
// reshape==1: Y written as (B,H,S,HD).
// ---------------------------------------------------------------------------
__global__ __launch_bounds__(256) void gemm_tf32(const float* __restrict__ X,
                                                 const float* __restrict__ W,
                                                 const float* __restrict__ bias,
                                                 float* __restrict__ Y,
                                                 int reshape)
{
    __shared__ uint32_t As[BM * LDW];   // [m][k] tf32 bits (2560 words)
    __shared__ uint32_t Bs[BN * LDW];   // [n][k] tf32 bits (5120 words)

    const int K    = D_;
    const int tid  = threadIdx.x;
    const int lane = tid & 31;
    const int warp = tid >> 5;
    const int wm   = warp >> 2;          // 0..1 -> 64-row slab
    const int wn   = warp & 3;           // 0..3 -> 64-col slab
    const int lr   = lane >> 2;          // 0..7
    const int lc   = lane & 3;           // 0..3
    const int m0   = blockIdx.y * BM;
    const int n0   = blockIdx.x * BN;

    // Loader mapping: thread covers row (tid>>2)+l*64, float4 unit (tid&3).
    const int lrow = tid >> 2;           // 0..63
    const int lcol = (tid & 3) << 2;     // 0,4,8,12
    const float* Xp = X + (size_t)(m0 + lrow) * K + lcol;
    const float* Wp = W + (size_t)(n0 + lrow) * K + lcol;

    float acc[4][8][4];
#pragma unroll
    for (int i = 0; i < 4; i++)
#pragma unroll
        for (int j = 0; j < 8; j++)
#pragma unroll
            for (int c = 0; c < 4; c++) acc[i][j][c] = 0.f;

    const int NKT = K / BK;   // 128
    for (int kt = 0; kt < NKT; ++kt) {
        const int ko = kt * BK;

        // Batched LDG: A 2 float4/thread, B 4 float4/thread (24 temp regs).
        float4 pa[2], pb[4];
#pragma unroll
        for (int l = 0; l < 2; l++)
            pa[l] = *reinterpret_cast<const float4*>(Xp + (size_t)(l * 64) * K + ko);
#pragma unroll
        for (int l = 0; l < 4; l++)
            pb[l] = *reinterpret_cast<const float4*>(Wp + (size_t)(l * 64) * K + ko);

        __syncthreads();   // previous tile's readers done
#pragma unroll
        for (int l = 0; l < 2; l++) {
            *reinterpret_cast<uint4*>(&As[(lrow + l * 64) * LDW + lcol]) =
                make_uint4(f2tf32(pa[l].x), f2tf32(pa[l].y), f2tf32(pa[l].z), f2tf32(pa[l].w));
        }
#pragma unroll
        for (int l = 0; l < 4; l++) {
            *reinterpret_cast<uint4*>(&Bs[(lrow + l * 64) * LDW + lcol]) =
                make_uint4(f2tf32(pb[l].x), f2tf32(pb[l].y), f2tf32(pb[l].z), f2tf32(pb[l].w));
        }
        __syncthreads();   // tile ready

#pragma unroll
        for (int ks = 0; ks < 2; ++ks) {
            const int k0 = ks * 8;
            uint32_t af[4][4], bf[8][2];
#pragma unroll
            for (int mf = 0; mf < 4; mf++) {
                const int r = wm * 64 + mf * 16 + lr;
                af[mf][0] = As[r * LDW + k0 + lc];
                af[mf][1] = As[(r + 8) * LDW + k0 + lc];
                af[mf][2] = As[r * LDW + k0 + 4 + lc];
                af[mf][3] = As[(r + 8) * LDW + k0 + 4 + lc];
            }
#pragma unroll
            for (int nf = 0; nf < 8; nf++) {
                const int n = wn * 64 + nf * 8 + lr;
                bf[nf][0] = Bs[n * LDW + k0 + lc];
                bf[nf][1] = Bs[n * LDW + k0 + 4 + lc];
            }
#pragma unroll
            for (int mf = 0; mf < 4; mf++)
#pragma unroll
                for (int nf = 0; nf < 8; nf++)
                    mma_tf32(acc[mf][nf], af[mf][0], af[mf][1], af[mf][2], af[mf][3],
                             bf[nf][0], bf[nf][1]);
        }
    }

    // Epilogue.  Each warp's 64-col span lies within one head (64 | 128).
    const int hh = (n0 + wn * 64) >> 7;
#pragma unroll
    for (int mf = 0; mf < 4; mf++) {
#pragma unroll
        for (int nf = 0; nf < 8; nf++) {
            const int nloc = wn * 64 + nf * 8 + lc * 2;
            const int n    = n0 + nloc;
            const float b0 = bias[n];
            const float b1 = bias[n + 1];
#pragma unroll
            for (int half = 0; half < 2; half++) {
                const int m = m0 + wm * 64 + mf * 16 + lr + half * 8;
                const float v0 = acc[mf][nf][half * 2 + 0] + b0;
                const float v1 = acc[mf][nf][half * 2 + 1] + b1;
                size_t idx;
                if (reshape) {
                    const int bb = m >> 11;
                    const int ss = m & (S_ - 1);
                    const int hd = n & (HD_ - 1);
                    idx = (((size_t)(bb * H_ + hh)) * S_ + ss) * HD_ + hd;
                } else {
                    idx = (size_t)m * D_ + n;
                }
                *reinterpret_cast<float2*>(Y + idx) = make_float2(v0, v1);
            }
        }
    }
}

// ---------------------------------------------------------------------------
// Causal flash attention, tf32 mma.sync, FA2-style register-resident P.
// (round-7 version, byte-identical — best measured configuration)
// ---------------------------------------------------------------------------
__global__ __launch_bounds__(256) void flash_tc(const float* __restrict__ Qg,
                                                const float* __restrict__ Kg,
                                                const float* __restrict__ Vg,
                                                float* __restrict__ ctx)
{
    extern __shared__ uint32_t smu[];
    uint32_t* Qs = smu;                       // [FBR][QLD] tf32
    uint32_t* Ks = Qs + FBR * QLD;            // [FBC][QLD] tf32
    uint32_t* Vs = Ks + FBC * QLD;            // [FBC][QLD] tf32

    const int bh  = blockIdx.y;
    const int qt  = (int)gridDim.x - 1 - (int)blockIdx.x;   // heavy blocks first
    const int q0  = qt * FBR;
    const int tid = threadIdx.x;
    const int lane = tid & 31;
    const int warp = tid >> 5;
    const int lr = lane >> 2;      // 0..7
    const int lc = lane & 3;       // 0..3
    const int wrow = warp * 16;    // warp's first query row (local)

    const float* Qb = Qg + ((size_t)bh * S_ + q0) * HD_;
    const float* Kb = Kg + (size_t)bh * S_ * HD_;
    const float* Vb = Vg + (size_t)bh * S_ * HD_;

    // Load Q tile (128x128) as tf32.
#pragma unroll
    for (int l = 0; l < 16; ++l) {
        int f   = tid + l * 256;
        int row = f >> 5;
        int c4  = (f & 31) << 2;
        float4 v = *reinterpret_cast<const float4*>(Qb + (size_t)row * HD_ + c4);
        *reinterpret_cast<uint4*>(&Qs[row * QLD + c4]) =
            make_uint4(f2tf32(v.x), f2tf32(v.y), f2tf32(v.z), f2tf32(v.w));
    }

    // O accumulator: warp tile 16(m) x 128(n) = 16 n-frags.
    float o[16][4];
#pragma unroll
    for (int j = 0; j < 16; j++)
#pragma unroll
        for (int c = 0; c < 4; c++) o[j][c] = 0.f;

    // Per-thread softmax state: rows (wrow+lr) and (wrow+lr+8), quad-replicated.
    float m0 = -1e30f, m1 = -1e30f, l0 = 0.f, l1 = 0.f;

    const float scale = 0.08838834764831845f;  // 1/sqrt(128)
    const unsigned FULL = 0xffffffffu;
    const int srcA = (lane & 28) | (lc >> 1);  // quad lane holding cols {lc&~1, lc|1}
    const int srcB = srcA + 2;                 // quad lane holding cols {4+..}

    const int ntiles = 2 * qt + 2;
    for (int t = 0; t < ntiles; ++t) {
        const int k0 = t * FBC;
        __syncthreads();   // prior PV readers of Ks/Vs done

        // Load K,V tiles (64x128 each) as tf32.
#pragma unroll
        for (int l = 0; l < 8; ++l) {
            int f   = tid + l * 256;
            int row = f >> 5;
            int c4  = (f & 31) << 2;
            float4 kv = *reinterpret_cast<const float4*>(Kb + (size_t)(k0 + row) * HD_ + c4);
            *reinterpret_cast<uint4*>(&Ks[row * QLD + c4]) =
                make_uint4(f2tf32(kv.x), f2tf32(kv.y), f2tf32(kv.z), f2tf32(kv.w));
            float4 vv = *reinterpret_cast<const float4*>(Vb + (size_t)(k0 + row) * HD_ + c4);
            *reinterpret_cast<uint4*>(&Vs[row * QLD + c4]) =
                make_uint4(f2tf32(vv.x), f2tf32(vv.y), f2tf32(vv.z), f2tf32(vv.w));
        }
        __syncthreads();

        // S = Q @ K^T : warp tile 16x64 -> 8 n-frags, K-dim 128.
        float sacc[8][4];
#pragma unroll
        for (int j = 0; j < 8; j++)
#pragma unroll
            for (int c = 0; c < 4; c++) sacc[j][c] = 0.f;

#pragma unroll
        for (int ks = 0; ks < 16; ++ks) {
            const int k = ks * 8;
            uint32_t a0 = Qs[(wrow + lr) * QLD + k + lc];
            uint32_t a1 = Qs[(wrow + lr + 8) * QLD + k + lc];
            uint32_t a2 = Qs[(wrow + lr) * QLD + k + 4 + lc];
            uint32_t a3 = Qs[(wrow + lr + 8) * QLD + k + 4 + lc];
#pragma unroll
            for (int nf = 0; nf < 8; nf++) {
                const int n = nf * 8 + lr;
                uint32_t b0 = Ks[n * QLD + k + lc];
                uint32_t b1 = Ks[n * QLD + k + 4 + lc];
                mma_tf32(sacc[nf], a0, a1, a2, a3, b0, b1);
            }
        }

        // Scale + causal mask (register-resident).
        const bool needmask = (k0 + FBC - 1 > q0);
        const int r0g = q0 + wrow + lr;
        const int r1g = r0g + 8;
#pragma unroll
        for (int nf = 0; nf < 8; nf++) {
#pragma unroll
            for (int c = 0; c < 4; c++) {
                const int cg = k0 + nf * 8 + lc * 2 + (c & 1);
                float v = sacc[nf][c] * scale;
                if (needmask && cg > ((c & 2) ? r1g : r0g)) v = -1e9f;
                sacc[nf][c] = v;
            }
        }

        // Register softmax: row maxima via quad shfl.
        float tm0 = -1e30f, tm1 = -1e30f;
#pragma unroll
        for (int nf = 0; nf < 8; nf++) {
            tm0 = fmaxf(tm0, fmaxf(sacc[nf][0], sacc[nf][1]));
            tm1 = fmaxf(tm1, fmaxf(sacc[nf][2], sacc[nf][3]));
        }
        tm0 = fmaxf(tm0, __shfl_xor_sync(FULL, tm0, 1));
        tm0 = fmaxf(tm0, __shfl_xor_sync(FULL, tm0, 2));
        tm1 = fmaxf(tm1, __shfl_xor_sync(FULL, tm1, 1));
        tm1 = fmaxf(tm1, __shfl_xor_sync(FULL, tm1, 2));

        const float mn0 = fmaxf(m0, tm0);
        const float mn1 = fmaxf(m1, tm1);
        const float al0 = __expf(m0 - mn0);
        const float al1 = __expf(m1 - mn1);

        // Exponentiate in registers; keep probs as tf32 bits.
        uint32_t pb[8][4];
        float sum0 = 0.f, sum1 = 0.f;
#pragma unroll
        for (int nf = 0; nf < 8; nf++) {
            float p0 = __expf(sacc[nf][0] - mn0);
            float p1 = __expf(sacc[nf][1] - mn0);
            float p2 = __expf(sacc[nf][2] - mn1);
            float p3 = __expf(sacc[nf][3] - mn1);
            sum0 += p0 + p1;
            sum1 += p2 + p3;
            pb[nf][0] = f2tf32(p0); pb[nf][1] = f2tf32(p1);
            pb[nf][2] = f2tf32(p2); pb[nf][3] = f2tf32(p3);
        }
        sum0 += __shfl_xor_sync(FULL, sum0, 1);
        sum0 += __shfl_xor_sync(FULL, sum0, 2);
        sum1 += __shfl_xor_sync(FULL, sum1, 1);
        sum1 += __shfl_xor_sync(FULL, sum1, 2);
        l0 = l0 * al0 + sum0;
        l1 = l1 * al1 + sum1;
        m0 = mn0;
        m1 = mn1;

        // Rescale O.
#pragma unroll
        for (int nf = 0; nf < 16; nf++) {
            o[nf][0] *= al0; o[nf][1] *= al0;
            o[nf][2] *= al1; o[nf][3] *= al1;
        }

        // O += P @ V.  A-frags assembled from pb via quad shfls.
        const bool odd = (lc & 1);
#pragma unroll
        for (int ks = 0; ks < 8; ++ks) {
            uint32_t t00 = __shfl_sync(FULL, pb[ks][0], srcA);
            uint32_t t01 = __shfl_sync(FULL, pb[ks][1], srcA);
            uint32_t t10 = __shfl_sync(FULL, pb[ks][2], srcA);
            uint32_t t11 = __shfl_sync(FULL, pb[ks][3], srcA);
            uint32_t u00 = __shfl_sync(FULL, pb[ks][0], srcB);
            uint32_t u01 = __shfl_sync(FULL, pb[ks][1], srcB);
            uint32_t u10 = __shfl_sync(FULL, pb[ks][2], srcB);
            uint32_t u11 = __shfl_sync(FULL, pb[ks][3], srcB);
            uint32_t a0 = odd ? t01 : t00;
            uint32_t a1 = odd ? t11 : t10;
            uint32_t a2 = odd ? u01 : u00;
            uint32_t a3 = odd ? u11 : u10;
            const int k = ks * 8;
#pragma unroll
            for (int nf = 0; nf < 16; nf++) {
                const int n = nf * 8 + lr;
                uint32_t b0 = Vs[(k + lc) * QLD + n];
                uint32_t b1 = Vs[(k + 4 + lc) * QLD + n];
                mma_tf32(o[nf], a0, a1, a2, a3, b0, b1);
            }
        }
    }

    // Epilogue: normalize rows by 1/l and write ctx in (B,S,D).
    const int bb = bh / H_;
    const int hh = bh % H_;
    const float inv0 = 1.0f / l0;
    const float inv1 = 1.0f / l1;
    float* dst0 = ctx + ((size_t)bb * S_ + q0 + wrow + lr) * D_ + hh * HD_;
    float* dst1 = ctx + ((size_t)bb * S_ + q0 + wrow + lr + 8) * D_ + hh * HD_;
#pragma unroll
    for (int nf = 0; nf < 16; nf++) {
        const int cloc = nf * 8 + lc * 2;
        *reinterpret_cast<float2*>(dst0 + cloc) =
            make_float2(o[nf][0] * inv0, o[nf][1] * inv0);
        *reinterpret_cast<float2*>(dst1 + cloc) =
            make_float2(o[nf][2] * inv1, o[nf][3] * inv1);
    }
}

// ---------------------------------------------------------------------------
// kernel_launch
// ---------------------------------------------------------------------------
extern "C" void kernel_launch(void* const* d_in, const int* in_sizes, int n_in,
                              void* d_out, int out_size)
{
    const float* X  = (const float*)d_in[0];
    const float* Wq = (const float*)d_in[2];
    const float* bq = (const float*)d_in[3];
    const float* Wk = (const float*)d_in[4];
    const float* bk = (const float*)d_in[5];
    const float* Wv = (const float*)d_in[6];
    const float* bv = (const float*)d_in[7];
    const float* Wo = (const float*)d_in[8];
    const float* bo = (const float*)d_in[9];

    float* out = (float*)d_out;
    const size_t OFF = (size_t)B_ * S_ * D_;
    float* kout = out + OFF;
    float* vout = out + 2 * OFF;

    static float* qbuf = nullptr;
    static float* cbuf = nullptr;
    static const int FSMEM = (FBR * QLD + 2 * FBC * QLD) * (int)sizeof(uint32_t);
    if (qbuf == nullptr) {
        cudaGetSymbolAddress((void**)&qbuf, g_q);
        cudaGetSymbolAddress((void**)&cbuf, g_ctx);
        cudaFuncSetAttribute(flash_tc, cudaFuncAttributeMaxDynamicSharedMemorySize, FSMEM);
    }

    dim3 gg(D_ / BN, M_ / BM);   // (8, 32) = 256 CTAs
    gemm_tf32<<<gg, 256>>>(X, Wq, bq, qbuf, 1);
    gemm_tf32<<<gg, 256>>>(X, Wk, bk, kout, 1);
    gemm_tf32<<<gg, 256>>>(X, Wv, bv, vout, 1);

    flash_tc<<<dim3(S_ / FBR, B_ * H_), 256, FSMEM>>>(qbuf, kout, vout, cbuf);

    gemm_tf32<<<gg, 256>>>(cbuf, Wo, bo, out, 0);
}

// round 15
// speedup vs baseline: 1.4544x; 1.4544x over previous
#include <cuda_runtime.h>
#include <math.h>
#include <stdint.h>

// Problem constants
#define B_  2
#define S_  2048
#define D_  2048
#define H_  16
#define HD_ 128
#define M_  (B_*S_)   // 4096 rows

// GEMM tiling (round-5 proven config): block 128x128x32, warp tile 64x32
#define BM 128
#define BN 128
#define BK 32
#define LDW 36        // BK + 4 pad words

// Flash-attention tiling
#define FBR 128
#define FBC 64
#define QLD 132       // Q/K pitch: 132 mod 32 == 4  -> QK frags conflict-free
#define VLD 136       // V   pitch: 136 mod 32 == 8  -> PV frags conflict-free

// Scratch (device globals: allocation-free rule)
__device__ float g_q[(size_t)M_ * D_];    // Q in (B,H,S,HD) layout
__device__ float g_ctx[(size_t)M_ * D_];  // attention context in (B,S,D) layout

__device__ __forceinline__ uint32_t f2tf32(float x) {
    uint32_t u;
    asm("cvt.rna.tf32.f32 %0, %1;" : "=r"(u) : "f"(x));
    return u;
}

__device__ __forceinline__ void mma_tf32(float c[4], uint32_t a0, uint32_t a1,
                                         uint32_t a2, uint32_t a3,
                                         uint32_t b0, uint32_t b1) {
    asm volatile(
        "mma.sync.aligned.m16n8k8.row.col.f32.tf32.tf32.f32 "
        "{%0,%1,%2,%3}, {%4,%5,%6,%7}, {%8,%9}, {%0,%1,%2,%3};"
        : "+f"(c[0]), "+f"(c[1]), "+f"(c[2]), "+f"(c[3])
        : "r"(a0), "r"(a1), "r"(a2), "r"(a3), "r"(b0), "r"(b1));
}

// ---------------------------------------------------------------------------
// GEMM (tf32 mma.sync): Y = X @ W^T + bias.
// Round-5 configuration EXACTLY (best measured: ~253 us/GEMM):
// 128x128x32 block, 8 warps as 2(M)x4(N), warp tile 64x32, static smem,
// cross-tile register prefetch.
// ---------------------------------------------------------------------------
__global__ __launch_bounds__(256) void gemm_tf32(const float* __restrict__ X,
                                                 const float* __restrict__ W,
                                                 const float* __restrict__ bias,
                                                 float* __restrict__ Y,
                                                 int reshape)
{
    __shared__ uint32_t As[BM * LDW];
    __shared__ uint32_t Bs[BN * LDW];

    const int K    = D_;
    const int tid  = threadIdx.x;
    const int lane = tid & 31;
    const int warp = tid >> 5;
    const int wm   = warp >> 2;
    const int wn   = warp & 3;
    const int lr   = lane >> 2;
    const int lc   = lane & 3;
    const int m0   = blockIdx.y * BM;
    const int n0   = blockIdx.x * BN;

    const int lrow = tid >> 3;
    const int lcol = (tid & 7) << 2;
    const float* Xp = X + (size_t)(m0 + lrow) * K + lcol;
    const float* Wp = W + (size_t)(n0 + lrow) * K + lcol;

    float acc[4][4][4];
#pragma unroll
    for (int i = 0; i < 4; i++)
#pragma unroll
        for (int j = 0; j < 4; j++)
#pragma unroll
            for (int c = 0; c < 4; c++) acc[i][j][c] = 0.f;

    float4 pa[4], pb[4];
#pragma unroll
    for (int l = 0; l < 4; l++) {
        pa[l] = *reinterpret_cast<const float4*>(Xp + (size_t)(l * 32) * K);
        pb[l] = *reinterpret_cast<const float4*>(Wp + (size_t)(l * 32) * K);
    }
#pragma unroll
    for (int l = 0; l < 4; l++) {
        uint32_t* a = &As[(lrow + l * 32) * LDW + lcol];
        a[0] = f2tf32(pa[l].x); a[1] = f2tf32(pa[l].y);
        a[2] = f2tf32(pa[l].z); a[3] = f2tf32(pa[l].w);
        uint32_t* b = &Bs[(lrow + l * 32) * LDW + lcol];
        b[0] = f2tf32(pb[l].x); b[1] = f2tf32(pb[l].y);
        b[2] = f2tf32(pb[l].z); b[3] = f2tf32(pb[l].w);
    }
    __syncthreads();

    const int NKT = K / BK;
    for (int kt = 0; kt < NKT; ++kt) {
        const bool has_next = (kt + 1 < NKT);
        if (has_next) {
            const int ko = (kt + 1) * BK;
#pragma unroll
            for (int l = 0; l < 4; l++) {
                pa[l] = *reinterpret_cast<const float4*>(Xp + (size_t)(l * 32) * K + ko);
                pb[l] = *reinterpret_cast<const float4*>(Wp + (size_t)(l * 32) * K + ko);
            }
        }
#pragma unroll
        for (int ks = 0; ks < 4; ++ks) {
            const int k0 = ks * 8;
            uint32_t af[4][4], bf[4][2];
#pragma unroll
            for (int mf = 0; mf < 4; mf++) {
                const int r = wm * 64 + mf * 16 + lr;
                af[mf][0] = As[r * LDW + k0 + lc];
                af[mf][1] = As[(r + 8) * LDW + k0 + lc];
                af[mf][2] = As[r * LDW + k0 + 4 + lc];
                af[mf][3] = As[(r + 8) * LDW + k0 + 4 + lc];
            }
#pragma unroll
            for (int nf = 0; nf < 4; nf++) {
                const int n = wn * 32 + nf * 8 + lr;
                bf[nf][0] = Bs[n * LDW + k0 + lc];
                bf[nf][1] = Bs[n * LDW + k0 + 4 + lc];
            }
#pragma unroll
            for (int mf = 0; mf < 4; mf++)
#pragma unroll
                for (int nf = 0; nf < 4; nf++)
                    mma_tf32(acc[mf][nf], af[mf][0], af[mf][1], af[mf][2], af[mf][3],
                             bf[nf][0], bf[nf][1]);
        }
        __syncthreads();
        if (has_next) {
#pragma unroll
            for (int l = 0; l < 4; l++) {
                uint32_t* a = &As[(lrow + l * 32) * LDW + lcol];
                a[0] = f2tf32(pa[l].x); a[1] = f2tf32(pa[l].y);
                a[2] = f2tf32(pa[l].z); a[3] = f2tf32(pa[l].w);
                uint32_t* b = &Bs[(lrow + l * 32) * LDW + lcol];
                b[0] = f2tf32(pb[l].x); b[1] = f2tf32(pb[l].y);
                b[2] = f2tf32(pb[l].z); b[3] = f2tf32(pb[l].w);
            }
            __syncthreads();
        }
    }

    const int hh = n0 >> 7;
#pragma unroll
    for (int mf = 0; mf < 4; mf++) {
#pragma unroll
        for (int nf = 0; nf < 4; nf++) {
            const int nloc = wn * 32 + nf * 8 + lc * 2;
            const int n    = n0 + nloc;
            const float b0 = bias[n];
            const float b1 = bias[n + 1];
#pragma unroll
            for (int half = 0; half < 2; half++) {
                const int m = m0 + wm * 64 + mf * 16 + lr + half * 8;
                const float v0 = acc[mf][nf][half * 2 + 0] + b0;
                const float v1 = acc[mf][nf][half * 2 + 1] + b1;
                size_t idx;
                if (reshape) {
                    const int bb = m >> 11;
                    const int ss = m & (S_ - 1);
                    const int hd = n & (HD_ - 1);
                    idx = (((size_t)(bb * H_ + hh)) * S_ + ss) * HD_ + hd;
                } else {
                    idx = (size_t)m * D_ + n;
                }
                *reinterpret_cast<float2*>(Y + idx) = make_float2(v0, v1);
            }
        }
    }
}

// ---------------------------------------------------------------------------
// Causal flash attention, tf32 mma.sync, FA2-style register-resident P.
// Round-7 structure; ONLY change: V stored with pitch VLD=136 so the PV
// B-fragment loads (bank = 8*lc + lr) are conflict-free (was 2-way at 132).
// ---------------------------------------------------------------------------
__global__ __launch_bounds__(256) void flash_tc(const float* __restrict__ Qg,
                                                const float* __restrict__ Kg,
                                                const float* __restrict__ Vg,
                                                float* __restrict__ ctx)
{
    extern __shared__ uint32_t smu[];
    uint32_t* Qs = smu;                       // [FBR][QLD] tf32
    uint32_t* Ks = Qs + FBR * QLD;            // [FBC][QLD] tf32
    uint32_t* Vs = Ks + FBC * QLD;            // [FBC][VLD] tf32

    const int bh  = blockIdx.y;
    const int qt  = (int)gridDim.x - 1 - (int)blockIdx.x;   // heavy blocks first
    const int q0  = qt * FBR;
    const int tid = threadIdx.x;
    const int lane = tid & 31;
    const int warp = tid >> 5;
    const int lr = lane >> 2;      // 0..7
    const int lc = lane & 3;       // 0..3
    const int wrow = warp * 16;    // warp's first query row (local)

    const float* Qb = Qg + ((size_t)bh * S_ + q0) * HD_;
    const float* Kb = Kg + (size_t)bh * S_ * HD_;
    const float* Vb = Vg + (size_t)bh * S_ * HD_;

    // Load Q tile (128x128) as tf32.
#pragma unroll
    for (int l = 0; l < 16; ++l) {
        int f   = tid + l * 256;
        int row = f >> 5;
        int c4  = (f & 31) << 2;
        float4 v = *reinterpret_cast<const float4*>(Qb + (size_t)row * HD_ + c4);
        *reinterpret_cast<uint4*>(&Qs[row * QLD + c4]) =
            make_uint4(f2tf32(v.x), f2tf32(v.y), f2tf32(v.z), f2tf32(v.w));
    }

    // O accumulator: warp tile 16(m) x 128(n) = 16 n-frags.
    float o[16][4];
#pragma unroll
    for (int j = 0; j < 16; j++)
#pragma unroll
        for (int c = 0; c < 4; c++) o[j][c] = 0.f;

    // Per-thread softmax state: rows (wrow+lr) and (wrow+lr+8), quad-replicated.
    float m0 = -1e30f, m1 = -1e30f, l0 = 0.f, l1 = 0.f;

    const float scale = 0.08838834764831845f;  // 1/sqrt(128)
    const unsigned FULL = 0xffffffffu;
    const int srcA = (lane & 28) | (lc >> 1);  // quad lane holding cols {lc&~1, lc|1}
    const int srcB = srcA + 2;                 // quad lane holding cols {4+..}

    const int ntiles = 2 * qt + 2;
    for (int t = 0; t < ntiles; ++t) {
        const int k0 = t * FBC;
        __syncthreads();   // prior PV readers of Ks/Vs done

        // Load K,V tiles (64x128 each) as tf32.  V uses pitch VLD.
#pragma unroll
        for (int l = 0; l < 8; ++l) {
            int f   = tid + l * 256;
            int row = f >> 5;
            int c4  = (f & 31) << 2;
            float4 kv = *reinterpret_cast<const float4*>(Kb + (size_t)(k0 + row) * HD_ + c4);
            *reinterpret_cast<uint4*>(&Ks[row * QLD + c4]) =
                make_uint4(f2tf32(kv.x), f2tf32(kv.y), f2tf32(kv.z), f2tf32(kv.w));
            float4 vv = *reinterpret_cast<const float4*>(Vb + (size_t)(k0 + row) * HD_ + c4);
            *reinterpret_cast<uint4*>(&Vs[row * VLD + c4]) =
                make_uint4(f2tf32(vv.x), f2tf32(vv.y), f2tf32(vv.z), f2tf32(vv.w));
        }
        __syncthreads();

        // S = Q @ K^T : warp tile 16x64 -> 8 n-frags, K-dim 128.
        float sacc[8][4];
#pragma unroll
        for (int j = 0; j < 8; j++)
#pragma unroll
            for (int c = 0; c < 4; c++) sacc[j][c] = 0.f;

#pragma unroll
        for (int ks = 0; ks < 16; ++ks) {
            const int k = ks * 8;
            uint32_t a0 = Qs[(wrow + lr) * QLD + k + lc];
            uint32_t a1 = Qs[(wrow + lr + 8) * QLD + k + lc];
            uint32_t a2 = Qs[(wrow + lr) * QLD + k + 4 + lc];
            uint32_t a3 = Qs[(wrow + lr + 8) * QLD + k + 4 + lc];
#pragma unroll
            for (int nf = 0; nf < 8; nf++) {
                const int n = nf * 8 + lr;
                uint32_t b0 = Ks[n * QLD + k + lc];
                uint32_t b1 = Ks[n * QLD + k + 4 + lc];
                mma_tf32(sacc[nf], a0, a1, a2, a3, b0, b1);
            }
        }

        // Scale + causal mask (register-resident).
        const bool needmask = (k0 + FBC - 1 > q0);
        const int r0g = q0 + wrow + lr;
        const int r1g = r0g + 8;
#pragma unroll
        for (int nf = 0; nf < 8; nf++) {
#pragma unroll
            for (int c = 0; c < 4; c++) {
                const int cg = k0 + nf * 8 + lc * 2 + (c & 1);
                float v = sacc[nf][c] * scale;
                if (needmask && cg > ((c & 2) ? r1g : r0g)) v = -1e9f;
                sacc[nf][c] = v;
            }
        }

        // Register softmax: row maxima via quad shfl.
        float tm0 = -1e30f, tm1 = -1e30f;
#pragma unroll
        for (int nf = 0; nf < 8; nf++) {
            tm0 = fmaxf(tm0, fmaxf(sacc[nf][0], sacc[nf][1]));
            tm1 = fmaxf(tm1, fmaxf(sacc[nf][2], sacc[nf][3]));
        }
        tm0 = fmaxf(tm0, __shfl_xor_sync(FULL, tm0, 1));
        tm0 = fmaxf(tm0, __shfl_xor_sync(FULL, tm0, 2));
        tm1 = fmaxf(tm1, __shfl_xor_sync(FULL, tm1, 1));
        tm1 = fmaxf(tm1, __shfl_xor_sync(FULL, tm1, 2));

        const float mn0 = fmaxf(m0, tm0);
        const float mn1 = fmaxf(m1, tm1);
        const float al0 = __expf(m0 - mn0);
        const float al1 = __expf(m1 - mn1);

        // Exponentiate in registers; keep probs as tf32 bits.
        uint32_t pb[8][4];
        float sum0 = 0.f, sum1 = 0.f;
#pragma unroll
        for (int nf = 0; nf < 8; nf++) {
            float p0 = __expf(sacc[nf][0] - mn0);
            float p1 = __expf(sacc[nf][1] - mn0);
            float p2 = __expf(sacc[nf][2] - mn1);
            float p3 = __expf(sacc[nf][3] - mn1);
            sum0 += p0 + p1;
            sum1 += p2 + p3;
            pb[nf][0] = f2tf32(p0); pb[nf][1] = f2tf32(p1);
            pb[nf][2] = f2tf32(p2); pb[nf][3] = f2tf32(p3);
        }
        sum0 += __shfl_xor_sync(FULL, sum0, 1);
        sum0 += __shfl_xor_sync(FULL, sum0, 2);
        sum1 += __shfl_xor_sync(FULL, sum1, 1);
        sum1 += __shfl_xor_sync(FULL, sum1, 2);
        l0 = l0 * al0 + sum0;
        l1 = l1 * al1 + sum1;
        m0 = mn0;
        m1 = mn1;

        // Rescale O.
#pragma unroll
        for (int nf = 0; nf < 16; nf++) {
            o[nf][0] *= al0; o[nf][1] *= al0;
            o[nf][2] *= al1; o[nf][3] *= al1;
        }

        // O += P @ V.  A-frags assembled from pb via quad shfls.
        const bool odd = (lc & 1);
#pragma unroll
        for (int ks = 0; ks < 8; ++ks) {
            uint32_t t00 = __shfl_sync(FULL, pb[ks][0], srcA);
            uint32_t t01 = __shfl_sync(FULL, pb[ks][1], srcA);
            uint32_t t10 = __shfl_sync(FULL, pb[ks][2], srcA);
            uint32_t t11 = __shfl_sync(FULL, pb[ks][3], srcA);
            uint32_t u00 = __shfl_sync(FULL, pb[ks][0], srcB);
            uint32_t u01 = __shfl_sync(FULL, pb[ks][1], srcB);
            uint32_t u10 = __shfl_sync(FULL, pb[ks][2], srcB);
            uint32_t u11 = __shfl_sync(FULL, pb[ks][3], srcB);
            uint32_t a0 = odd ? t01 : t00;
            uint32_t a1 = odd ? t11 : t10;
            uint32_t a2 = odd ? u01 : u00;
            uint32_t a3 = odd ? u11 : u10;
            const int k = ks * 8;
#pragma unroll
            for (int nf = 0; nf < 16; nf++) {
                const int n = nf * 8 + lr;
                uint32_t b0 = Vs[(k + lc) * VLD + n];
                uint32_t b1 = Vs[(k + 4 + lc) * VLD + n];
                mma_tf32(o[nf], a0, a1, a2, a3, b0, b1);
            }
        }
    }

    // Epilogue: normalize rows by 1/l and write ctx in (B,S,D).
    const int bb = bh / H_;
    const int hh = bh % H_;
    const float inv0 = 1.0f / l0;
    const float inv1 = 1.0f / l1;
    float* dst0 = ctx + ((size_t)bb * S_ + q0 + wrow + lr) * D_ + hh * HD_;
    float* dst1 = ctx + ((size_t)bb * S_ + q0 + wrow + lr + 8) * D_ + hh * HD_;
#pragma unroll
    for (int nf = 0; nf < 16; nf++) {
        const int cloc = nf * 8 + lc * 2;
        *reinterpret_cast<float2*>(dst0 + cloc) =
            make_float2(o[nf][0] * inv0, o[nf][1] * inv0);
        *reinterpret_cast<float2*>(dst1 + cloc) =
            make_float2(o[nf][2] * inv1, o[nf][3] * inv1);
    }
}

// ---------------------------------------------------------------------------
// kernel_launch
// ---------------------------------------------------------------------------
extern "C" void kernel_launch(void* const* d_in, const int* in_sizes, int n_in,
                              void* d_out, int out_size)
{
    const float* X  = (const float*)d_in[0];
    const float* Wq = (const float*)d_in[2];
    const float* bq = (const float*)d_in[3];
    const float* Wk = (const float*)d_in[4];
    const float* bk = (const float*)d_in[5];
    const float* Wv = (const float*)d_in[6];
    const float* bv = (const float*)d_in[7];
    const float* Wo = (const float*)d_in[8];
    const float* bo = (const float*)d_in[9];

    float* out = (float*)d_out;
    const size_t OFF = (size_t)B_ * S_ * D_;
    float* kout = out + OFF;
    float* vout = out + 2 * OFF;

    static float* qbuf = nullptr;
    static float* cbuf = nullptr;
    static const int FSMEM = (FBR * QLD + FBC * QLD + FBC * VLD) * (int)sizeof(uint32_t);
    if (qbuf == nullptr) {
        cudaGetSymbolAddress((void**)&qbuf, g_q);
        cudaGetSymbolAddress((void**)&cbuf, g_ctx);
        cudaFuncSetAttribute(flash_tc, cudaFuncAttributeMaxDynamicSharedMemorySize, FSMEM);
    }

    dim3 gg(D_ / BN, M_ / BM);   // (16, 32)
    gemm_tf32<<<gg, 256>>>(X, Wq, bq, qbuf, 1);
    gemm_tf32<<<gg, 256>>>(X, Wk, bk, kout, 1);
    gemm_tf32<<<gg, 256>>>(X, Wv, bv, vout, 1);

    flash_tc<<<dim3(S_ / FBR, B_ * H_), 256, FSMEM>>>(qbuf, kout, vout, cbuf);

    gemm_tf32<<<gg, 256>>>(cbuf, Wo, bo, out, 0);
}